// round 7
// baseline (speedup 1.0000x reference)
#include <cuda_runtime.h>
#include <cuda_fp16.h>
#include <cstdint>

// Problem constants
#define DM   1024
#define DI   2048
#define DS   16
#define BB   2
#define LL   2048
#define MM   (BB*LL)         // 4096 tokens
#define GCH  8               // scan chunks
#define CLEN (LL/GCH)        // 256 steps per chunk

// ---------------- scratch (device globals) -----------------------------------
__device__ float g_xz [(size_t)MM * 2 * DI];   // x_proj | silu(z)  (fp32)
__device__ float g_dt [(size_t)MM * DI];       // softplus dt       (fp32)
__device__ float g_A2 [DI * DS];               // -exp(A_log)*log2e

// split fp16 operand arrays (hi / lo)
__device__ __half g_xh   [(size_t)MM * DM],     g_xl   [(size_t)MM * DM];
__device__ __half g_Winh [(size_t)2*DI * DM];
__device__ __half g_Wdth [(size_t)DI * DI];
__device__ __half g_Wouth[(size_t)DM * DI];
__device__ __half g_xacth[(size_t)MM * DI],     g_xactl[(size_t)MM * DI];
__device__ __half g_ygh  [(size_t)MM * DI],     g_ygl  [(size_t)MM * DI];

// chunked-scan intermediates
__device__ float g_Sdv [(size_t)BB * DI * GCH];
__device__ float g_hout[(size_t)BB * DI * GCH * DS];
__device__ float g_hin [(size_t)BB * DI * GCH * DS];

// ---------------- scalar helpers ---------------------------------------------
__device__ __forceinline__ float ex2f(float x) {
    float y; asm("ex2.approx.ftz.f32 %0, %1;" : "=f"(y) : "f"(x)); return y;
}
__device__ __forceinline__ float siluf(float v) {
    return __fdividef(v, 1.0f + __expf(-v));
}
__device__ __forceinline__ float softplusf(float v) {
    return (v > 20.0f) ? v : log1pf(__expf(v));
}
__device__ __forceinline__ uint32_t smem_u32(const void* p) {
    uint32_t a;
    asm("{ .reg .u64 t; cvta.to.shared.u64 t, %1; cvt.u32.u64 %0, t; }" : "=r"(a) : "l"(p));
    return a;
}

// ---------------- PTX primitives (baseline ISA only) --------------------------
#define CP16(dst, src) \
    asm volatile("cp.async.cg.shared.global [%0], [%1], 16;" :: "r"(dst), "l"(src) : "memory")
#define CP_COMMIT() asm volatile("cp.async.commit_group;" ::: "memory")
#define CP_WAIT(n)  asm volatile("cp.async.wait_group %0;" :: "n"(n) : "memory")

#define LDSM4(r, addr) \
    asm volatile("ldmatrix.sync.aligned.m8n8.x4.shared.b16 {%0,%1,%2,%3}, [%4];" \
        : "=r"((r)[0]), "=r"((r)[1]), "=r"((r)[2]), "=r"((r)[3]) : "r"(addr))

#define MMA_F16(d, a, b0, b1) \
    asm volatile("mma.sync.aligned.m16n8k16.row.col.f32.f16.f16.f32 " \
        "{%0,%1,%2,%3}, {%4,%5,%6,%7}, {%8,%9}, {%0,%1,%2,%3};" \
        : "+f"((d)[0]), "+f"((d)[1]), "+f"((d)[2]), "+f"((d)[3]) \
        : "r"((a)[0]), "r"((a)[1]), "r"((a)[2]), "r"((a)[3]), "r"(b0), "r"(b1))

#define SWZ(off) ((off) ^ (((off) >> 3) & 0x70))

// ---------------- split-fp16 NT-GEMM via mma.sync -----------------------------
// C[M,N] = A[M,K]*B[N,K]^T, A = Ah+Al (fp16), B = Bh (fp16). 2 MMA passes.
// CTA tile 128(M) x 256(N), BK=64, 512 threads (16 warps: 4M x 4N, 32x64 warp
// tiles), 3-stage cp.async pipeline (192KB SMEM), one barrier per K-chunk.
static constexpr int TN          = 256;
static constexpr int STAGE_BYTES = 65536;              // Ah(16K)|Al(16K)|Bh(32K)
static constexpr int GEMM_SMEM   = 3 * STAGE_BYTES;    // 192KB

template<int N, int K, int EPI>
__global__ void __launch_bounds__(512, 1)
mma_gemm(const __half* __restrict__ Ah, const __half* __restrict__ Al,
         const __half* __restrict__ Bh,
         float* __restrict__ C, const float* __restrict__ bias)
{
    extern __shared__ __align__(1024) uint8_t smem[];
    const uint32_t sb = smem_u32(smem);
    const int tid = threadIdx.x, lane = tid & 31, wid = tid >> 5;
    const int wm = wid & 3, wn = wid >> 2;            // 4 x 4 warp grid
    const int bm = blockIdx.y * 128, bn = blockIdx.x * TN;
    constexpr int NC = K / 64;

    // ---- cp.async mapping: 512 rows per stage (Ah 128 | Al 128 | Bh 256),
    //      each thread owns one row (8 x 16B granules) ------------------------
    const __half* gsrc;
    uint32_t sregion;
    if (tid < 128)      { gsrc = Ah + (size_t)(bm + tid) * K;        sregion = (uint32_t)tid * 128; }
    else if (tid < 256) { gsrc = Al + (size_t)(bm + tid - 128) * K;  sregion = 16384u + (uint32_t)(tid - 128) * 128; }
    else                { gsrc = Bh + (size_t)(bn + tid - 256) * K;  sregion = 32768u + (uint32_t)(tid - 256) * 128; }
    uint32_t dOff[8];
#pragma unroll
    for (int j = 0; j < 8; j++) dOff[j] = SWZ(sregion + (uint32_t)j * 16);

    // ---- ldmatrix lane offsets ----
    const int rA = (lane & 7) + ((lane >> 3) & 1) * 8;
    const int sA = ((lane >> 4) & 1) * 16;
    const uint32_t aOff = SWZ((uint32_t)(wm * 32 + rA) * 128 + sA);
    const int rB = (lane & 7) + ((lane >> 4) & 1) * 8;
    const int sB = ((lane >> 3) & 1) * 16;
    const uint32_t bOff = SWZ((uint32_t)(wn * 64 + rB) * 128 + sB);

    float acc[2][8][4];
#pragma unroll
    for (int i = 0; i < 2; i++)
#pragma unroll
        for (int j = 0; j < 8; j++)
#pragma unroll
            for (int q = 0; q < 4; q++) acc[i][j][q] = 0.f;

    auto issue = [&](int c) {
        const uint32_t s0 = sb + (uint32_t)(c % 3) * STAGE_BYTES;
        const int k0 = c * 64;
#pragma unroll
        for (int j = 0; j < 8; j++)
            CP16(s0 + dOff[j], gsrc + k0 + j * 8);
        CP_COMMIT();
    };

    issue(0);
    issue(1);
    for (int c = 0; c < NC; c++) {
        if (c + 2 < NC) { CP_WAIT(1); __syncthreads(); issue(c + 2); }
        else            { CP_WAIT(0); __syncthreads(); }

        const uint32_t s0 = sb + (uint32_t)(c % 3) * STAGE_BYTES;
        const uint32_t aB = s0 + aOff;
        const uint32_t bB = s0 + 32768u + bOff;
#pragma unroll
        for (int kk = 0; kk < 4; kk++) {
            const uint32_t kx = (uint32_t)kk * 32;
            uint32_t ah[2][4], al[2][4], bh[4][4];
#pragma unroll
            for (int mf = 0; mf < 2; mf++) {
                LDSM4(ah[mf], (aB + (uint32_t)mf * 2048) ^ kx);
                LDSM4(al[mf], (aB + 16384u + (uint32_t)mf * 2048) ^ kx);
            }
#pragma unroll
            for (int g = 0; g < 4; g++)
                LDSM4(bh[g], (bB + (uint32_t)g * 2048) ^ kx);
#pragma unroll
            for (int mf = 0; mf < 2; mf++)
#pragma unroll
                for (int g = 0; g < 4; g++)
#pragma unroll
                    for (int h = 0; h < 2; h++) {
                        float* d = acc[mf][g * 2 + h];
                        MMA_F16(d, ah[mf], bh[g][2 * h], bh[g][2 * h + 1]);
                        MMA_F16(d, al[mf], bh[g][2 * h], bh[g][2 * h + 1]);
                    }
        }
    }

    // ---- epilogue ----
    const int qr = lane >> 2, qc = lane & 3;
    const bool do_silu = (EPI == 1) && (bn >= (N >> 1));
#pragma unroll
    for (int mf = 0; mf < 2; mf++) {
        const int row0 = bm + wm * 32 + mf * 16 + qr;
#pragma unroll
        for (int p = 0; p < 2; p++) {
            float* cr = C + (size_t)(row0 + p * 8) * N + bn + wn * 64 + qc * 2;
#pragma unroll
            for (int nf = 0; nf < 8; nf++) {
                float vx = acc[mf][nf][2 * p];
                float vy = acc[mf][nf][2 * p + 1];
                if (EPI == 1) {
                    if (do_silu) { vx = siluf(vx); vy = siluf(vy); }
                } else if (EPI == 2) {
                    const int col = bn + wn * 64 + nf * 8 + qc * 2;
                    vx = softplusf(vx + bias[col]);
                    vy = softplusf(vy + bias[col + 1]);
                }
                float2 v; v.x = vx; v.y = vy;
                *(float2*)(cr + nf * 8) = v;
            }
        }
    }
}

// ---------------- fp32 -> (hi, lo) fp16 split ---------------------------------
__global__ void split_kernel(const float* __restrict__ in,
                             __half* __restrict__ oh,
                             __half* __restrict__ ol, int n4)
{
    int i = blockIdx.x * blockDim.x + threadIdx.x;
    if (i >= n4) return;
    float4 v = ((const float4*)in)[i];
    __half2 ha = __floats2half2_rn(v.x, v.y);
    __half2 hb = __floats2half2_rn(v.z, v.w);
    ((__half2*)oh)[2 * i]     = ha;
    ((__half2*)oh)[2 * i + 1] = hb;
    if (ol) {
        __half2 la = __floats2half2_rn(v.x - __low2float(ha), v.y - __high2float(ha));
        __half2 lb = __floats2half2_rn(v.z - __low2float(hb), v.w - __high2float(hb));
        ((__half2*)ol)[2 * i]     = la;
        ((__half2*)ol)[2 * i + 1] = lb;
    }
}

// ---------------- depthwise causal conv + SiLU + split -------------------------
__global__ void conv_silu_kernel(const float* __restrict__ cw,
                                 const float* __restrict__ cb)
{
    int idx = blockIdx.x * blockDim.x + threadIdx.x;
    if (idx >= MM * DI) return;
    const int c = idx & (DI - 1);
    const int m = idx >> 11;
    const int t = m & (LL - 1);

    const float* p = g_xz + (size_t)m * (2 * DI) + c;
    const float4 w = ((const float4*)cw)[c];
    float acc = cb[c] + w.w * p[0];
    if (t >= 1) acc += w.z * p[-(2 * DI)];
    if (t >= 2) acc += w.y * p[-2 * (2 * DI)];
    if (t >= 3) acc += w.x * p[-3 * (2 * DI)];
    const float v = siluf(acc);
    const __half h = __float2half_rn(v);
    g_xacth[idx] = h;
    g_xactl[idx] = __float2half_rn(v - __half2float(h));
}

// ---------------- A2 = -exp(A_log) * log2(e) -----------------------------------
__global__ void prep_A2_kernel(const float* __restrict__ A_log)
{
    int i = blockIdx.x * blockDim.x + threadIdx.x;
    if (i < DI * DS) g_A2[i] = -expf(A_log[i]) * 1.4426950408889634f;
}

// ---------------- chunked scan: pass A (per-chunk partials) --------------------
__global__ void __launch_bounds__(128)
scanA_kernel()
{
    const int tid = threadIdx.x;
    const int sg  = tid & 3;
    const int cl  = tid >> 2;
    const int g   = blockIdx.x & (GCH - 1);
    const int cb  = (blockIdx.x >> 3) & 63;
    const int b   = blockIdx.x >> 9;
    const int c   = (cb << 5) + cl;

    float a2[4];
#pragma unroll
    for (int s = 0; s < 4; s++) a2[s] = g_A2[c * DS + sg * 4 + s];

    const size_t base = (size_t)b * LL * DI + (size_t)g * CLEN * DI + c;

    float h0 = 0.f, h1 = 0.f, h2 = 0.f, h3 = 0.f, sdv = 0.f;
    float px[8], pd[8];
#pragma unroll
    for (int u = 0; u < 8; u++) {
        const size_t o = base + (size_t)u * DI;
        px[u] = __half2float(g_xacth[o]) + __half2float(g_xactl[o]);
        pd[u] = g_dt[o];
    }

    for (int t0 = 0; t0 < CLEN; t0 += 8) {
        float cx[8], cd[8];
#pragma unroll
        for (int u = 0; u < 8; u++) { cx[u] = px[u]; cd[u] = pd[u]; }
        if (t0 + 8 < CLEN) {
#pragma unroll
            for (int u = 0; u < 8; u++) {
                const size_t o = base + (size_t)(t0 + 8 + u) * DI;
                px[u] = __half2float(g_xacth[o]) + __half2float(g_xactl[o]);
                pd[u] = g_dt[o];
            }
        }
#pragma unroll
        for (int u = 0; u < 8; u++) {
            const float dv  = cd[u];
            const float dtx = dv * cx[u];
            sdv += dv;
            h0 = ex2f(dv * a2[0]) * h0 + dtx;
            h1 = ex2f(dv * a2[1]) * h1 + dtx;
            h2 = ex2f(dv * a2[2]) * h2 + dtx;
            h3 = ex2f(dv * a2[3]) * h3 + dtx;
        }
    }

    const size_t idx = ((size_t)b * DI + c) * GCH + g;
    if (sg == 0) g_Sdv[idx] = sdv;
    float* ho = g_hout + idx * DS + sg * 4;
    ho[0] = h0; ho[1] = h1; ho[2] = h2; ho[3] = h3;
}

// ---------------- chunked scan: pass B (sequential combine) --------------------
__global__ void __launch_bounds__(256)
scanB_kernel()
{
    const int i = blockIdx.x * blockDim.x + threadIdx.x;
    if (i >= BB * DI * 4) return;
    const int sg = i & 3;
    const int c  = (i >> 2) & (DI - 1);
    const int b  = i >> 13;

    float a2[4];
#pragma unroll
    for (int s = 0; s < 4; s++) a2[s] = g_A2[c * DS + sg * 4 + s];

    float h[4] = {0.f, 0.f, 0.f, 0.f};
    const size_t row = ((size_t)b * DI + c) * GCH;
#pragma unroll
    for (int g = 0; g < GCH; g++) {
        const size_t idx = row + g;
        const float sdv = g_Sdv[idx];
        float* hi = g_hin  + idx * DS + sg * 4;
        const float* ho = g_hout + idx * DS + sg * 4;
#pragma unroll
        for (int s = 0; s < 4; s++) {
            hi[s] = h[s];
            h[s] = ex2f(a2[s] * sdv) * h[s] + ho[s];
        }
    }
}

// ---------------- chunked scan: pass C (recompute + gate + split) --------------
__global__ void __launch_bounds__(128)
scanC_kernel(const float* __restrict__ Dp)
{
    const int tid = threadIdx.x;
    const int sg  = tid & 3;
    const int cl  = tid >> 2;
    const int g   = blockIdx.x & (GCH - 1);
    const int cb  = (blockIdx.x >> 3) & 63;
    const int b   = blockIdx.x >> 9;
    const int c   = (cb << 5) + cl;

    float a2[4];
#pragma unroll
    for (int s = 0; s < 4; s++) a2[s] = g_A2[c * DS + sg * 4 + s];
    const float dpc = Dp[c];

    const size_t base = (size_t)b * LL * DI + (size_t)g * CLEN * DI + c;
    const size_t zoff = (size_t)b * LL * (2 * DI) + (size_t)g * CLEN * (2 * DI) + DI + c;

    const size_t idx = ((size_t)b * DI + c) * GCH + g;
    const float* hi = g_hin + idx * DS + sg * 4;
    float h0 = hi[0], h1 = hi[1], h2 = hi[2], h3 = hi[3];

    float px[8], pd[8];
#pragma unroll
    for (int u = 0; u < 8; u++) {
        const size_t o = base + (size_t)u * DI;
        px[u] = __half2float(g_xacth[o]) + __half2float(g_xactl[o]);
        pd[u] = g_dt[o];
    }

    for (int t0 = 0; t0 < CLEN; t0 += 8) {
        float cx[8], cd[8];
#pragma unroll
        for (int u = 0; u < 8; u++) { cx[u] = px[u]; cd[u] = pd[u]; }
        if (t0 + 8 < CLEN) {
#pragma unroll
            for (int u = 0; u < 8; u++) {
                const size_t o = base + (size_t)(t0 + 8 + u) * DI;
                px[u] = __half2float(g_xacth[o]) + __half2float(g_xactl[o]);
                pd[u] = g_dt[o];
            }
        }
#pragma unroll
        for (int u = 0; u < 8; u++) {
            const float xv  = cx[u];
            const float dv  = cd[u];
            const float dtx = dv * xv;
            h0 = ex2f(dv * a2[0]) * h0 + dtx;
            h1 = ex2f(dv * a2[1]) * h1 + dtx;
            h2 = ex2f(dv * a2[2]) * h2 + dtx;
            h3 = ex2f(dv * a2[3]) * h3 + dtx;
            float sum = (h0 + h1) + (h2 + h3);
            sum += __shfl_xor_sync(0xffffffffu, sum, 1);
            sum += __shfl_xor_sync(0xffffffffu, sum, 2);
            if (sg == 0) {
                const float zs = g_xz[zoff + (size_t)(t0 + u) * (2 * DI)];
                const float v  = (sum + dpc * xv) * zs;
                const size_t o = base + (size_t)(t0 + u) * DI;
                const __half hh = __float2half_rn(v);
                g_ygh[o] = hh;
                g_ygl[o] = __float2half_rn(v - __half2float(hh));
            }
        }
    }
}

// ---------------- launch -------------------------------------------------------
extern "C" void kernel_launch(void* const* d_in, const int* in_sizes, int n_in,
                              void* d_out, int out_size)
{
    (void)in_sizes; (void)n_in; (void)out_size;
    const float* x     = (const float*)d_in[0];
    const float* W_in  = (const float*)d_in[1];
    const float* cw    = (const float*)d_in[2];
    const float* cb    = (const float*)d_in[3];
    const float* A_log = (const float*)d_in[4];
    const float* Dp    = (const float*)d_in[5];
    const float* W_dt  = (const float*)d_in[6];
    const float* b_dt  = (const float*)d_in[7];
    const float* W_out = (const float*)d_in[8];
    float* out = (float*)d_out;

    float *xz, *dt;
    __half *xh, *xl, *winh, *wdth, *wouth, *xacth, *xactl, *ygh, *ygl;
    cudaGetSymbolAddress((void**)&xz,    g_xz);
    cudaGetSymbolAddress((void**)&dt,    g_dt);
    cudaGetSymbolAddress((void**)&xh,    g_xh);
    cudaGetSymbolAddress((void**)&xl,    g_xl);
    cudaGetSymbolAddress((void**)&winh,  g_Winh);
    cudaGetSymbolAddress((void**)&wdth,  g_Wdth);
    cudaGetSymbolAddress((void**)&wouth, g_Wouth);
    cudaGetSymbolAddress((void**)&xacth, g_xacth);
    cudaGetSymbolAddress((void**)&xactl, g_xactl);
    cudaGetSymbolAddress((void**)&ygh,   g_ygh);
    cudaGetSymbolAddress((void**)&ygl,   g_ygl);

    cudaFuncSetAttribute(mma_gemm<2 * DI, DM, 1>,
                         cudaFuncAttributeMaxDynamicSharedMemorySize, GEMM_SMEM);
    cudaFuncSetAttribute(mma_gemm<DI, DI, 2>,
                         cudaFuncAttributeMaxDynamicSharedMemorySize, GEMM_SMEM);
    cudaFuncSetAttribute(mma_gemm<DM, DI, 0>,
                         cudaFuncAttributeMaxDynamicSharedMemorySize, GEMM_SMEM);

    // launches #1..#3 (profiler captures the 4th launch -> gemm1)
    prep_A2_kernel<<<(DI * DS + 255) / 256, 256>>>(A_log);
    split_kernel<<<(MM * DM / 4 + 255) / 256, 256>>>(x,    xh,   xl,      MM * DM / 4);
    split_kernel<<<(2 * DI * DM / 4 + 255) / 256, 256>>>(W_in, winh, nullptr, 2 * DI * DM / 4);

    // #4: GEMM1: xz = x @ W_in^T  (silu fused on z half)   <-- profiled
    mma_gemm<2 * DI, DM, 1><<<dim3((2 * DI) / TN, MM / 128), 512, GEMM_SMEM>>>(
        xh, xl, winh, xz, nullptr);

    split_kernel<<<(DI * DI / 4 + 255) / 256, 256>>>(W_dt, wdth, nullptr, DI * DI / 4);
    conv_silu_kernel<<<(MM * DI + 255) / 256, 256>>>(cw, cb);

    // GEMM2: dt = softplus(x_act @ W_dt^T + b_dt)
    mma_gemm<DI, DI, 2><<<dim3(DI / TN, MM / 128), 512, GEMM_SMEM>>>(
        xacth, xactl, wdth, dt, b_dt);

    split_kernel<<<(DM * DI / 4 + 255) / 256, 256>>>(W_out, wouth, nullptr, DM * DI / 4);

    // chunked scan
    scanA_kernel<<<BB * (DI / 32) * GCH, 128>>>();
    scanB_kernel<<<(BB * DI * 4 + 255) / 256, 256>>>();
    scanC_kernel<<<BB * (DI / 32) * GCH, 128>>>(Dp);

    // GEMM3: out = yg @ W_out^T
    mma_gemm<DM, DI, 0><<<dim3(DM / TN, MM / 128), 512, GEMM_SMEM>>>(
        ygh, ygl, wouth, out, nullptr);
}

// round 8
// speedup vs baseline: 1.3241x; 1.3241x over previous
#include <cuda_runtime.h>
#include <cuda_fp16.h>
#include <cstdint>

// Problem constants
#define DM   1024
#define DI   2048
#define DS   16
#define BB   2
#define LL   2048
#define MM   (BB*LL)         // 4096 tokens
#define GCH  8               // scan chunks
#define CLEN (LL/GCH)        // 256 steps per chunk

// ---------------- scratch (device globals) -----------------------------------
__device__ float g_xz [(size_t)MM * 2 * DI];   // x_proj | silu(z)  (fp32)
__device__ float g_dt [(size_t)MM * DI];       // softplus dt       (fp32)
__device__ float g_A2 [DI * DS];               // -exp(A_log)*log2e

// split fp16 operand arrays (hi / lo)
__device__ __half g_xh   [(size_t)MM * DM],     g_xl   [(size_t)MM * DM];
__device__ __half g_Winh [(size_t)2*DI * DM];
__device__ __half g_Wdth [(size_t)DI * DI];
__device__ __half g_Wouth[(size_t)DM * DI];
__device__ __half g_xacth[(size_t)MM * DI],     g_xactl[(size_t)MM * DI];
__device__ __half g_ygh  [(size_t)MM * DI];     // single fp16 (no lo)

// chunked-scan intermediates
__device__ float g_Sdv [(size_t)BB * DI * GCH];
__device__ float g_hout[(size_t)BB * DI * GCH * DS];
__device__ float g_hin [(size_t)BB * DI * GCH * DS];

// ---------------- scalar helpers ---------------------------------------------
__device__ __forceinline__ float ex2f(float x) {
    float y; asm("ex2.approx.ftz.f32 %0, %1;" : "=f"(y) : "f"(x)); return y;
}
__device__ __forceinline__ float siluf(float v) {
    return __fdividef(v, 1.0f + __expf(-v));
}
__device__ __forceinline__ float softplusf(float v) {
    return (v > 20.0f) ? v : log1pf(__expf(v));
}
__device__ __forceinline__ uint32_t smem_u32(const void* p) {
    uint32_t a;
    asm("{ .reg .u64 t; cvta.to.shared.u64 t, %1; cvt.u32.u64 %0, t; }" : "=r"(a) : "l"(p));
    return a;
}

// ---------------- PTX primitives (baseline ISA only) --------------------------
#define CP16(dst, src) \
    asm volatile("cp.async.cg.shared.global [%0], [%1], 16;" :: "r"(dst), "l"(src) : "memory")
#define CP_COMMIT() asm volatile("cp.async.commit_group;" ::: "memory")
#define CP_WAIT(n)  asm volatile("cp.async.wait_group %0;" :: "n"(n) : "memory")

#define LDSM4(r, addr) \
    asm volatile("ldmatrix.sync.aligned.m8n8.x4.shared.b16 {%0,%1,%2,%3}, [%4];" \
        : "=r"((r)[0]), "=r"((r)[1]), "=r"((r)[2]), "=r"((r)[3]) : "r"(addr))

#define MMA_F16(d, a, b0, b1) \
    asm volatile("mma.sync.aligned.m16n8k16.row.col.f32.f16.f16.f32 " \
        "{%0,%1,%2,%3}, {%4,%5,%6,%7}, {%8,%9}, {%0,%1,%2,%3};" \
        : "+f"((d)[0]), "+f"((d)[1]), "+f"((d)[2]), "+f"((d)[3]) \
        : "r"((a)[0]), "r"((a)[1]), "r"((a)[2]), "r"((a)[3]), "r"(b0), "r"(b1))

#define SWZ(off) ((off) ^ (((off) >> 3) & 0x70))

// ---------------- split-fp16 NT-GEMM via mma.sync -----------------------------
// C[M,N] = A[M,K]*B[N,K]^T. APASS=2: A = Ah+Al (fp16), APASS=1: A = Ah only.
// B = Bh (fp16). 128x128 CTA tile, BK=64, 512 threads (16 warps: 4M x 4N,
// 32x32 warp tiles), 4-stage cp.async pipeline (192KB), 1 barrier per chunk.
// (Round-6 proven config; Round-7 32x64 warp tiles regressed — reg pressure.)
static constexpr int STAGE_BYTES = 49152;                // Ah|Al|Bh x 16KB
static constexpr int GEMM_SMEM   = 4 * STAGE_BYTES;      // 192KB

template<int N, int K, int EPI, int APASS>
__global__ void __launch_bounds__(512, 1)
mma_gemm(const __half* __restrict__ Ah, const __half* __restrict__ Al,
         const __half* __restrict__ Bh,
         float* __restrict__ C, const float* __restrict__ bias)
{
    extern __shared__ __align__(1024) uint8_t smem[];
    const uint32_t sb = smem_u32(smem);
    const int tid = threadIdx.x, lane = tid & 31, wid = tid >> 5;
    const int wm = wid & 3, wn = wid >> 2;            // 4 x 4 warp grid
    const int bm = blockIdx.y * 128, bn = blockIdx.x * 128;
    constexpr int NC = K / 64;

    // ---- cp.async mapping: per stage 3 arrays x 128 rows x 128B --------------
    const int lrow = tid >> 2;                 // 0..127
    const int gp   = (tid & 3) * 2;            // 2 x 16B granules per array
    uint32_t dOff[2];
#pragma unroll
    for (int j = 0; j < 2; j++)
        dOff[j] = SWZ((uint32_t)lrow * 128 + (uint32_t)(gp + j) * 16);

    const __half* gAh = Ah + (size_t)(bm + lrow) * K;
    const __half* gAl = (APASS == 2) ? Al + (size_t)(bm + lrow) * K : nullptr;
    const __half* gBh = Bh + (size_t)(bn + lrow) * K;

    // ---- ldmatrix lane offsets ----
    const int rA = (lane & 7) + ((lane >> 3) & 1) * 8;
    const int sA = ((lane >> 4) & 1) * 16;
    const uint32_t aOff = SWZ((uint32_t)(wm * 32 + rA) * 128 + sA);
    const int rB = (lane & 7) + ((lane >> 4) & 1) * 8;
    const int sB = ((lane >> 3) & 1) * 16;
    const uint32_t bOff = SWZ((uint32_t)(wn * 32 + rB) * 128 + sB);

    float acc[2][4][4];
#pragma unroll
    for (int i = 0; i < 2; i++)
#pragma unroll
        for (int j = 0; j < 4; j++)
#pragma unroll
            for (int q = 0; q < 4; q++) acc[i][j][q] = 0.f;

    auto issue = [&](int c) {
        const uint32_t s0 = sb + (uint32_t)(c & 3) * STAGE_BYTES;
        const int k0 = c * 64;
#pragma unroll
        for (int j = 0; j < 2; j++) {
            const int ke = k0 + (gp + j) * 8;
            CP16(s0 +         dOff[j], gAh + ke);
            if (APASS == 2) CP16(s0 + 16384 + dOff[j], gAl + ke);
            CP16(s0 + 32768 + dOff[j], gBh + ke);
        }
        CP_COMMIT();
    };

    issue(0);
    issue(1);
    issue(2);
    for (int c = 0; c < NC; c++) {
        if (c + 3 < NC) { CP_WAIT(2); __syncthreads(); issue(c + 3); }
        else            { CP_WAIT(0); __syncthreads(); }

        const uint32_t s0 = sb + (uint32_t)(c & 3) * STAGE_BYTES;
        const uint32_t aB = s0 + aOff;
        const uint32_t bB = s0 + 32768 + bOff;
#pragma unroll
        for (int kk = 0; kk < 4; kk++) {
            const uint32_t kx = (uint32_t)kk * 32;
            uint32_t ah[2][4], al[2][4], bh[2][4];
#pragma unroll
            for (int mf = 0; mf < 2; mf++) {
                LDSM4(ah[mf], (aB + (uint32_t)mf * 2048) ^ kx);
                if (APASS == 2)
                    LDSM4(al[mf], (aB + 16384u + (uint32_t)mf * 2048) ^ kx);
            }
#pragma unroll
            for (int g = 0; g < 2; g++)
                LDSM4(bh[g], (bB + (uint32_t)g * 2048) ^ kx);
#pragma unroll
            for (int mf = 0; mf < 2; mf++)
#pragma unroll
                for (int g = 0; g < 2; g++)
#pragma unroll
                    for (int h = 0; h < 2; h++) {
                        float* d = acc[mf][g * 2 + h];
                        MMA_F16(d, ah[mf], bh[g][2 * h], bh[g][2 * h + 1]);
                        if (APASS == 2)
                            MMA_F16(d, al[mf], bh[g][2 * h], bh[g][2 * h + 1]);
                    }
        }
    }

    // ---- epilogue ----
    const int qr = lane >> 2, qc = lane & 3;
    const bool do_silu = (EPI == 1) && (bn >= (N >> 1));
#pragma unroll
    for (int mf = 0; mf < 2; mf++) {
        const int row0 = bm + wm * 32 + mf * 16 + qr;
#pragma unroll
        for (int p = 0; p < 2; p++) {
            float* cr = C + (size_t)(row0 + p * 8) * N + bn + wn * 32 + qc * 2;
#pragma unroll
            for (int nf = 0; nf < 4; nf++) {
                float vx = acc[mf][nf][2 * p];
                float vy = acc[mf][nf][2 * p + 1];
                if (EPI == 1) {
                    if (do_silu) { vx = siluf(vx); vy = siluf(vy); }
                } else if (EPI == 2) {
                    const int col = bn + wn * 32 + nf * 8 + qc * 2;
                    vx = softplusf(vx + bias[col]);
                    vy = softplusf(vy + bias[col + 1]);
                }
                float2 v; v.x = vx; v.y = vy;
                *(float2*)(cr + nf * 8) = v;
            }
        }
    }
}

// ---------------- fp32 -> (hi, lo) fp16 split ---------------------------------
__global__ void split_kernel(const float* __restrict__ in,
                             __half* __restrict__ oh,
                             __half* __restrict__ ol, int n4)
{
    int i = blockIdx.x * blockDim.x + threadIdx.x;
    if (i >= n4) return;
    float4 v = ((const float4*)in)[i];
    __half2 ha = __floats2half2_rn(v.x, v.y);
    __half2 hb = __floats2half2_rn(v.z, v.w);
    ((__half2*)oh)[2 * i]     = ha;
    ((__half2*)oh)[2 * i + 1] = hb;
    if (ol) {
        __half2 la = __floats2half2_rn(v.x - __low2float(ha), v.y - __high2float(ha));
        __half2 lb = __floats2half2_rn(v.z - __low2float(hb), v.w - __high2float(hb));
        ((__half2*)ol)[2 * i]     = la;
        ((__half2*)ol)[2 * i + 1] = lb;
    }
}

// ---------------- depthwise causal conv + SiLU + split -------------------------
__global__ void conv_silu_kernel(const float* __restrict__ cw,
                                 const float* __restrict__ cb)
{
    int idx = blockIdx.x * blockDim.x + threadIdx.x;
    if (idx >= MM * DI) return;
    const int c = idx & (DI - 1);
    const int m = idx >> 11;
    const int t = m & (LL - 1);

    const float* p = g_xz + (size_t)m * (2 * DI) + c;
    const float4 w = ((const float4*)cw)[c];
    float acc = cb[c] + w.w * p[0];
    if (t >= 1) acc += w.z * p[-(2 * DI)];
    if (t >= 2) acc += w.y * p[-2 * (2 * DI)];
    if (t >= 3) acc += w.x * p[-3 * (2 * DI)];
    const float v = siluf(acc);
    const __half h = __float2half_rn(v);
    g_xacth[idx] = h;
    g_xactl[idx] = __float2half_rn(v - __half2float(h));
}

// ---------------- A2 = -exp(A_log) * log2(e) -----------------------------------
__global__ void prep_A2_kernel(const float* __restrict__ A_log)
{
    int i = blockIdx.x * blockDim.x + threadIdx.x;
    if (i < DI * DS) g_A2[i] = -expf(A_log[i]) * 1.4426950408889634f;
}

// ---------------- chunked scan: pass A (per-chunk partials) --------------------
__global__ void __launch_bounds__(128)
scanA_kernel()
{
    const int tid = threadIdx.x;
    const int sg  = tid & 3;
    const int cl  = tid >> 2;
    const int g   = blockIdx.x & (GCH - 1);
    const int cb  = (blockIdx.x >> 3) & 63;
    const int b   = blockIdx.x >> 9;
    const int c   = (cb << 5) + cl;

    float a2[4];
#pragma unroll
    for (int s = 0; s < 4; s++) a2[s] = g_A2[c * DS + sg * 4 + s];

    const size_t base = (size_t)b * LL * DI + (size_t)g * CLEN * DI + c;

    float h0 = 0.f, h1 = 0.f, h2 = 0.f, h3 = 0.f, sdv = 0.f;
    float px[8], pd[8];
#pragma unroll
    for (int u = 0; u < 8; u++) {
        const size_t o = base + (size_t)u * DI;
        px[u] = __half2float(g_xacth[o]) + __half2float(g_xactl[o]);
        pd[u] = g_dt[o];
    }

    for (int t0 = 0; t0 < CLEN; t0 += 8) {
        float cx[8], cd[8];
#pragma unroll
        for (int u = 0; u < 8; u++) { cx[u] = px[u]; cd[u] = pd[u]; }
        if (t0 + 8 < CLEN) {
#pragma unroll
            for (int u = 0; u < 8; u++) {
                const size_t o = base + (size_t)(t0 + 8 + u) * DI;
                px[u] = __half2float(g_xacth[o]) + __half2float(g_xactl[o]);
                pd[u] = g_dt[o];
            }
        }
#pragma unroll
        for (int u = 0; u < 8; u++) {
            const float dv  = cd[u];
            const float dtx = dv * cx[u];
            sdv += dv;
            h0 = ex2f(dv * a2[0]) * h0 + dtx;
            h1 = ex2f(dv * a2[1]) * h1 + dtx;
            h2 = ex2f(dv * a2[2]) * h2 + dtx;
            h3 = ex2f(dv * a2[3]) * h3 + dtx;
        }
    }

    const size_t idx = ((size_t)b * DI + c) * GCH + g;
    if (sg == 0) g_Sdv[idx] = sdv;
    float* ho = g_hout + idx * DS + sg * 4;
    ho[0] = h0; ho[1] = h1; ho[2] = h2; ho[3] = h3;
}

// ---------------- chunked scan: pass B (sequential combine) --------------------
__global__ void __launch_bounds__(256)
scanB_kernel()
{
    const int i = blockIdx.x * blockDim.x + threadIdx.x;
    if (i >= BB * DI * 4) return;
    const int sg = i & 3;
    const int c  = (i >> 2) & (DI - 1);
    const int b  = i >> 13;

    float a2[4];
#pragma unroll
    for (int s = 0; s < 4; s++) a2[s] = g_A2[c * DS + sg * 4 + s];

    float h[4] = {0.f, 0.f, 0.f, 0.f};
    const size_t row = ((size_t)b * DI + c) * GCH;
#pragma unroll
    for (int g = 0; g < GCH; g++) {
        const size_t idx = row + g;
        const float sdv = g_Sdv[idx];
        float* hi = g_hin  + idx * DS + sg * 4;
        const float* ho = g_hout + idx * DS + sg * 4;
#pragma unroll
        for (int s = 0; s < 4; s++) {
            hi[s] = h[s];
            h[s] = ex2f(a2[s] * sdv) * h[s] + ho[s];
        }
    }
}

// ---------------- chunked scan: pass C (recompute + gate) ----------------------
__global__ void __launch_bounds__(128)
scanC_kernel(const float* __restrict__ Dp)
{
    const int tid = threadIdx.x;
    const int sg  = tid & 3;
    const int cl  = tid >> 2;
    const int g   = blockIdx.x & (GCH - 1);
    const int cb  = (blockIdx.x >> 3) & 63;
    const int b   = blockIdx.x >> 9;
    const int c   = (cb << 5) + cl;

    float a2[4];
#pragma unroll
    for (int s = 0; s < 4; s++) a2[s] = g_A2[c * DS + sg * 4 + s];
    const float dpc = Dp[c];

    const size_t base = (size_t)b * LL * DI + (size_t)g * CLEN * DI + c;
    const size_t zoff = (size_t)b * LL * (2 * DI) + (size_t)g * CLEN * (2 * DI) + DI + c;

    const size_t idx = ((size_t)b * DI + c) * GCH + g;
    const float* hi = g_hin + idx * DS + sg * 4;
    float h0 = hi[0], h1 = hi[1], h2 = hi[2], h3 = hi[3];

    float px[8], pd[8];
#pragma unroll
    for (int u = 0; u < 8; u++) {
        const size_t o = base + (size_t)u * DI;
        px[u] = __half2float(g_xacth[o]) + __half2float(g_xactl[o]);
        pd[u] = g_dt[o];
    }

    for (int t0 = 0; t0 < CLEN; t0 += 8) {
        float cx[8], cd[8];
#pragma unroll
        for (int u = 0; u < 8; u++) { cx[u] = px[u]; cd[u] = pd[u]; }
        if (t0 + 8 < CLEN) {
#pragma unroll
            for (int u = 0; u < 8; u++) {
                const size_t o = base + (size_t)(t0 + 8 + u) * DI;
                px[u] = __half2float(g_xacth[o]) + __half2float(g_xactl[o]);
                pd[u] = g_dt[o];
            }
        }
#pragma unroll
        for (int u = 0; u < 8; u++) {
            const float xv  = cx[u];
            const float dv  = cd[u];
            const float dtx = dv * xv;
            h0 = ex2f(dv * a2[0]) * h0 + dtx;
            h1 = ex2f(dv * a2[1]) * h1 + dtx;
            h2 = ex2f(dv * a2[2]) * h2 + dtx;
            h3 = ex2f(dv * a2[3]) * h3 + dtx;
            float sum = (h0 + h1) + (h2 + h3);
            sum += __shfl_xor_sync(0xffffffffu, sum, 1);
            sum += __shfl_xor_sync(0xffffffffu, sum, 2);
            if (sg == 0) {
                const float zs = g_xz[zoff + (size_t)(t0 + u) * (2 * DI)];
                const float v  = (sum + dpc * xv) * zs;
                g_ygh[base + (size_t)(t0 + u) * DI] = __float2half_rn(v);
            }
        }
    }
}

// ---------------- launch -------------------------------------------------------
extern "C" void kernel_launch(void* const* d_in, const int* in_sizes, int n_in,
                              void* d_out, int out_size)
{
    (void)in_sizes; (void)n_in; (void)out_size;
    const float* x     = (const float*)d_in[0];
    const float* W_in  = (const float*)d_in[1];
    const float* cw    = (const float*)d_in[2];
    const float* cb    = (const float*)d_in[3];
    const float* A_log = (const float*)d_in[4];
    const float* Dp    = (const float*)d_in[5];
    const float* W_dt  = (const float*)d_in[6];
    const float* b_dt  = (const float*)d_in[7];
    const float* W_out = (const float*)d_in[8];
    float* out = (float*)d_out;

    float *xz, *dt;
    __half *xh, *xl, *winh, *wdth, *wouth, *xacth, *xactl, *ygh;
    cudaGetSymbolAddress((void**)&xz,    g_xz);
    cudaGetSymbolAddress((void**)&dt,    g_dt);
    cudaGetSymbolAddress((void**)&xh,    g_xh);
    cudaGetSymbolAddress((void**)&xl,    g_xl);
    cudaGetSymbolAddress((void**)&winh,  g_Winh);
    cudaGetSymbolAddress((void**)&wdth,  g_Wdth);
    cudaGetSymbolAddress((void**)&wouth, g_Wouth);
    cudaGetSymbolAddress((void**)&xacth, g_xacth);
    cudaGetSymbolAddress((void**)&xactl, g_xactl);
    cudaGetSymbolAddress((void**)&ygh,   g_ygh);

    cudaFuncSetAttribute(mma_gemm<2 * DI, DM, 1, 2>,
                         cudaFuncAttributeMaxDynamicSharedMemorySize, GEMM_SMEM);
    cudaFuncSetAttribute(mma_gemm<DI, DI, 2, 2>,
                         cudaFuncAttributeMaxDynamicSharedMemorySize, GEMM_SMEM);
    cudaFuncSetAttribute(mma_gemm<DM, DI, 0, 1>,
                         cudaFuncAttributeMaxDynamicSharedMemorySize, GEMM_SMEM);

    // launches #1..#3 (profiler captures the 4th launch -> gemm1)
    prep_A2_kernel<<<(DI * DS + 255) / 256, 256>>>(A_log);
    split_kernel<<<(MM * DM / 4 + 255) / 256, 256>>>(x,    xh,   xl,      MM * DM / 4);
    split_kernel<<<(2 * DI * DM / 4 + 255) / 256, 256>>>(W_in, winh, nullptr, 2 * DI * DM / 4);

    // #4: GEMM1: xz = x @ W_in^T  (silu fused on z half)   <-- profiled
    mma_gemm<2 * DI, DM, 1, 2><<<dim3((2 * DI) / 128, MM / 128), 512, GEMM_SMEM>>>(
        xh, xl, winh, xz, nullptr);

    split_kernel<<<(DI * DI / 4 + 255) / 256, 256>>>(W_dt, wdth, nullptr, DI * DI / 4);
    conv_silu_kernel<<<(MM * DI + 255) / 256, 256>>>(cw, cb);

    // GEMM2: dt = softplus(x_act @ W_dt^T + b_dt)
    mma_gemm<DI, DI, 2, 2><<<dim3(DI / 128, MM / 128), 512, GEMM_SMEM>>>(
        xacth, xactl, wdth, dt, b_dt);

    split_kernel<<<(DM * DI / 4 + 255) / 256, 256>>>(W_out, wouth, nullptr, DM * DI / 4);

    // chunked scan
    scanA_kernel<<<BB * (DI / 32) * GCH, 128>>>();
    scanB_kernel<<<(BB * DI * 4 + 255) / 256, 256>>>();
    scanC_kernel<<<BB * (DI / 32) * GCH, 128>>>(Dp);

    // GEMM3: out = yg @ W_out^T  (single-pass A)
    mma_gemm<DM, DI, 0, 1><<<dim3(DM / 128, MM / 128), 512, GEMM_SMEM>>>(
        ygh, nullptr, wouth, out, nullptr);
}

// round 9
// speedup vs baseline: 1.7041x; 1.2870x over previous
#include <cuda_runtime.h>
#include <cuda_fp16.h>
#include <cstdint>

// Problem constants
#define DM   1024
#define DI   2048
#define DS   16
#define BB   2
#define LL   2048
#define MM   (BB*LL)         // 4096 tokens
#define GCH  8               // scan chunks
#define CLEN (LL/GCH)        // 256 steps per chunk

// ---------------- scratch (device globals) -----------------------------------
__device__ float g_xz [(size_t)MM * 2 * DI];   // x_proj | silu(z)  (fp32)
__device__ float g_dt [(size_t)MM * DI];       // softplus dt       (fp32)
__device__ float g_A2 [DI * DS];               // -exp(A_log)*log2e

// fp16 operand arrays
__device__ __half g_xh   [(size_t)MM * DM];
__device__ __half g_Winh [(size_t)2*DI * DM];
__device__ __half g_Wdth [(size_t)DI * DI];
__device__ __half g_Wouth[(size_t)DM * DI];
__device__ __half g_xacth[(size_t)MM * DI];
__device__ __half g_ygh  [(size_t)MM * DI];

// chunked-scan intermediates
__device__ float g_Sdv [(size_t)BB * DI * GCH];
__device__ float g_hout[(size_t)BB * DI * GCH * DS];
__device__ float g_hin [(size_t)BB * DI * GCH * DS];

// ---------------- scalar helpers ---------------------------------------------
__device__ __forceinline__ float ex2f(float x) {
    float y; asm("ex2.approx.ftz.f32 %0, %1;" : "=f"(y) : "f"(x)); return y;
}
__device__ __forceinline__ float siluf(float v) {
    return __fdividef(v, 1.0f + __expf(-v));
}
__device__ __forceinline__ float softplusf(float v) {
    return (v > 20.0f) ? v : log1pf(__expf(v));
}
__device__ __forceinline__ uint32_t smem_u32(const void* p) {
    uint32_t a;
    asm("{ .reg .u64 t; cvta.to.shared.u64 t, %1; cvt.u32.u64 %0, t; }" : "=r"(a) : "l"(p));
    return a;
}

// ---------------- PTX primitives (baseline ISA only) --------------------------
#define CP16(dst, src) \
    asm volatile("cp.async.cg.shared.global [%0], [%1], 16;" :: "r"(dst), "l"(src) : "memory")
#define CP_COMMIT() asm volatile("cp.async.commit_group;" ::: "memory")
#define CP_WAIT(n)  asm volatile("cp.async.wait_group %0;" :: "n"(n) : "memory")

#define LDSM4(r, addr) \
    asm volatile("ldmatrix.sync.aligned.m8n8.x4.shared.b16 {%0,%1,%2,%3}, [%4];" \
        : "=r"((r)[0]), "=r"((r)[1]), "=r"((r)[2]), "=r"((r)[3]) : "r"(addr))

#define MMA_F16(d, a, b0, b1) \
    asm volatile("mma.sync.aligned.m16n8k16.row.col.f32.f16.f16.f32 " \
        "{%0,%1,%2,%3}, {%4,%5,%6,%7}, {%8,%9}, {%0,%1,%2,%3};" \
        : "+f"((d)[0]), "+f"((d)[1]), "+f"((d)[2]), "+f"((d)[3]) \
        : "r"((a)[0]), "r"((a)[1]), "r"((a)[2]), "r"((a)[3]), "r"(b0), "r"(b1))

#define SWZ(off) ((off) ^ (((off) >> 3) & 0x70))

// ---------------- fp16 NT-GEMM via mma.sync ------------------------------------
// C[M,N] = A[M,K]*B[N,K]^T, single fp16 pass (B rounding dominates accuracy;
// A-lo recovery passes removed — modeled +~2e-4 each in quadrature).
// 128x128 CTA tile, BK=64, 512 threads (16 warps: 4M x 4N, 32x32 warp tiles),
// 6-stage cp.async pipeline (192KB), 1 barrier per chunk.
static constexpr int STAGE_BYTES = 32768;                // Ah(16K) | Bh(16K)
static constexpr int NSTAGE      = 6;
static constexpr int GEMM_SMEM   = NSTAGE * STAGE_BYTES; // 192KB

template<int N, int K, int EPI>
__global__ void __launch_bounds__(512, 1)
mma_gemm(const __half* __restrict__ Ah, const __half* __restrict__ Bh,
         float* __restrict__ C, const float* __restrict__ bias)
{
    extern __shared__ __align__(1024) uint8_t smem[];
    const uint32_t sb = smem_u32(smem);
    const int tid = threadIdx.x, lane = tid & 31, wid = tid >> 5;
    const int wm = wid & 3, wn = wid >> 2;            // 4 x 4 warp grid
    const int bm = blockIdx.y * 128, bn = blockIdx.x * 128;
    constexpr int NC = K / 64;

    // ---- cp.async mapping: per stage 2 arrays x 128 rows x 128B ---------------
    const int lrow = tid >> 2;                 // 0..127
    const int gp   = (tid & 3) * 2;            // 2 x 16B granules per array
    uint32_t dOff[2];
#pragma unroll
    for (int j = 0; j < 2; j++)
        dOff[j] = SWZ((uint32_t)lrow * 128 + (uint32_t)(gp + j) * 16);

    const __half* gAh = Ah + (size_t)(bm + lrow) * K;
    const __half* gBh = Bh + (size_t)(bn + lrow) * K;

    // ---- ldmatrix lane offsets ----
    const int rA = (lane & 7) + ((lane >> 3) & 1) * 8;
    const int sA = ((lane >> 4) & 1) * 16;
    const uint32_t aOff = SWZ((uint32_t)(wm * 32 + rA) * 128 + sA);
    const int rB = (lane & 7) + ((lane >> 4) & 1) * 8;
    const int sB = ((lane >> 3) & 1) * 16;
    const uint32_t bOff = SWZ((uint32_t)(wn * 32 + rB) * 128 + sB);

    float acc[2][4][4];
#pragma unroll
    for (int i = 0; i < 2; i++)
#pragma unroll
        for (int j = 0; j < 4; j++)
#pragma unroll
            for (int q = 0; q < 4; q++) acc[i][j][q] = 0.f;

    auto issue = [&](int c) {
        const uint32_t s0 = sb + (uint32_t)(c % NSTAGE) * STAGE_BYTES;
        const int k0 = c * 64;
#pragma unroll
        for (int j = 0; j < 2; j++) {
            const int ke = k0 + (gp + j) * 8;
            CP16(s0 +         dOff[j], gAh + ke);
            CP16(s0 + 16384 + dOff[j], gBh + ke);
        }
        CP_COMMIT();
    };

#pragma unroll
    for (int s = 0; s < NSTAGE - 1 && s < NC; s++) issue(s);

    for (int c = 0; c < NC; c++) {
        if (c + NSTAGE - 1 < NC) { CP_WAIT(NSTAGE - 2); __syncthreads(); issue(c + NSTAGE - 1); }
        else                     { CP_WAIT(0); __syncthreads(); }

        const uint32_t s0 = sb + (uint32_t)(c % NSTAGE) * STAGE_BYTES;
        const uint32_t aB = s0 + aOff;
        const uint32_t bB = s0 + 16384 + bOff;
#pragma unroll
        for (int kk = 0; kk < 4; kk++) {
            const uint32_t kx = (uint32_t)kk * 32;
            uint32_t ah[2][4], bh[2][4];
#pragma unroll
            for (int mf = 0; mf < 2; mf++)
                LDSM4(ah[mf], (aB + (uint32_t)mf * 2048) ^ kx);
#pragma unroll
            for (int g = 0; g < 2; g++)
                LDSM4(bh[g], (bB + (uint32_t)g * 2048) ^ kx);
#pragma unroll
            for (int mf = 0; mf < 2; mf++)
#pragma unroll
                for (int g = 0; g < 2; g++)
#pragma unroll
                    for (int h = 0; h < 2; h++)
                        MMA_F16(acc[mf][g * 2 + h], ah[mf], bh[g][2 * h], bh[g][2 * h + 1]);
        }
    }

    // ---- epilogue ----
    const int qr = lane >> 2, qc = lane & 3;
    const bool do_silu = (EPI == 1) && (bn >= (N >> 1));
#pragma unroll
    for (int mf = 0; mf < 2; mf++) {
        const int row0 = bm + wm * 32 + mf * 16 + qr;
#pragma unroll
        for (int p = 0; p < 2; p++) {
            float* cr = C + (size_t)(row0 + p * 8) * N + bn + wn * 32 + qc * 2;
#pragma unroll
            for (int nf = 0; nf < 4; nf++) {
                float vx = acc[mf][nf][2 * p];
                float vy = acc[mf][nf][2 * p + 1];
                if (EPI == 1) {
                    if (do_silu) { vx = siluf(vx); vy = siluf(vy); }
                } else if (EPI == 2) {
                    const int col = bn + wn * 32 + nf * 8 + qc * 2;
                    vx = softplusf(vx + bias[col]);
                    vy = softplusf(vy + bias[col + 1]);
                }
                float2 v; v.x = vx; v.y = vy;
                *(float2*)(cr + nf * 8) = v;
            }
        }
    }
}

// ---------------- fp32 -> fp16 convert (vectorized x4) -------------------------
__global__ void cvt_kernel(const float* __restrict__ in,
                           __half* __restrict__ oh, int n4)
{
    int i = blockIdx.x * blockDim.x + threadIdx.x;
    if (i >= n4) return;
    float4 v = ((const float4*)in)[i];
    ((__half2*)oh)[2 * i]     = __floats2half2_rn(v.x, v.y);
    ((__half2*)oh)[2 * i + 1] = __floats2half2_rn(v.z, v.w);
}

// ---------------- depthwise causal conv + SiLU ---------------------------------
__global__ void conv_silu_kernel(const float* __restrict__ cw,
                                 const float* __restrict__ cb)
{
    int idx = blockIdx.x * blockDim.x + threadIdx.x;
    if (idx >= MM * DI) return;
    const int c = idx & (DI - 1);
    const int m = idx >> 11;
    const int t = m & (LL - 1);

    const float* p = g_xz + (size_t)m * (2 * DI) + c;
    const float4 w = ((const float4*)cw)[c];
    float acc = cb[c] + w.w * p[0];
    if (t >= 1) acc += w.z * p[-(2 * DI)];
    if (t >= 2) acc += w.y * p[-2 * (2 * DI)];
    if (t >= 3) acc += w.x * p[-3 * (2 * DI)];
    g_xacth[idx] = __float2half_rn(siluf(acc));
}

// ---------------- A2 = -exp(A_log) * log2(e) -----------------------------------
__global__ void prep_A2_kernel(const float* __restrict__ A_log)
{
    int i = blockIdx.x * blockDim.x + threadIdx.x;
    if (i < DI * DS) g_A2[i] = -expf(A_log[i]) * 1.4426950408889634f;
}

// ---------------- chunked scan: pass A (per-chunk partials) --------------------
__global__ void __launch_bounds__(128)
scanA_kernel()
{
    const int tid = threadIdx.x;
    const int sg  = tid & 3;
    const int cl  = tid >> 2;
    const int g   = blockIdx.x & (GCH - 1);
    const int cb  = (blockIdx.x >> 3) & 63;
    const int b   = blockIdx.x >> 9;
    const int c   = (cb << 5) + cl;

    float a2[4];
#pragma unroll
    for (int s = 0; s < 4; s++) a2[s] = g_A2[c * DS + sg * 4 + s];

    const size_t base = (size_t)b * LL * DI + (size_t)g * CLEN * DI + c;

    float h0 = 0.f, h1 = 0.f, h2 = 0.f, h3 = 0.f, sdv = 0.f;
    float px[8], pd[8];
#pragma unroll
    for (int u = 0; u < 8; u++) {
        const size_t o = base + (size_t)u * DI;
        px[u] = __half2float(g_xacth[o]);
        pd[u] = g_dt[o];
    }

    for (int t0 = 0; t0 < CLEN; t0 += 8) {
        float cx[8], cd[8];
#pragma unroll
        for (int u = 0; u < 8; u++) { cx[u] = px[u]; cd[u] = pd[u]; }
        if (t0 + 8 < CLEN) {
#pragma unroll
            for (int u = 0; u < 8; u++) {
                const size_t o = base + (size_t)(t0 + 8 + u) * DI;
                px[u] = __half2float(g_xacth[o]);
                pd[u] = g_dt[o];
            }
        }
#pragma unroll
        for (int u = 0; u < 8; u++) {
            const float dv  = cd[u];
            const float dtx = dv * cx[u];
            sdv += dv;
            h0 = ex2f(dv * a2[0]) * h0 + dtx;
            h1 = ex2f(dv * a2[1]) * h1 + dtx;
            h2 = ex2f(dv * a2[2]) * h2 + dtx;
            h3 = ex2f(dv * a2[3]) * h3 + dtx;
        }
    }

    const size_t idx = ((size_t)b * DI + c) * GCH + g;
    if (sg == 0) g_Sdv[idx] = sdv;
    float* ho = g_hout + idx * DS + sg * 4;
    ho[0] = h0; ho[1] = h1; ho[2] = h2; ho[3] = h3;
}

// ---------------- chunked scan: pass B (sequential combine) --------------------
__global__ void __launch_bounds__(256)
scanB_kernel()
{
    const int i = blockIdx.x * blockDim.x + threadIdx.x;
    if (i >= BB * DI * 4) return;
    const int sg = i & 3;
    const int c  = (i >> 2) & (DI - 1);
    const int b  = i >> 13;

    float a2[4];
#pragma unroll
    for (int s = 0; s < 4; s++) a2[s] = g_A2[c * DS + sg * 4 + s];

    float h[4] = {0.f, 0.f, 0.f, 0.f};
    const size_t row = ((size_t)b * DI + c) * GCH;
#pragma unroll
    for (int g = 0; g < GCH; g++) {
        const size_t idx = row + g;
        const float sdv = g_Sdv[idx];
        float* hi = g_hin  + idx * DS + sg * 4;
        const float* ho = g_hout + idx * DS + sg * 4;
#pragma unroll
        for (int s = 0; s < 4; s++) {
            hi[s] = h[s];
            h[s] = ex2f(a2[s] * sdv) * h[s] + ho[s];
        }
    }
}

// ---------------- chunked scan: pass C (recompute + gate) ----------------------
__global__ void __launch_bounds__(128)
scanC_kernel(const float* __restrict__ Dp)
{
    const int tid = threadIdx.x;
    const int sg  = tid & 3;
    const int cl  = tid >> 2;
    const int g   = blockIdx.x & (GCH - 1);
    const int cb  = (blockIdx.x >> 3) & 63;
    const int b   = blockIdx.x >> 9;
    const int c   = (cb << 5) + cl;

    float a2[4];
#pragma unroll
    for (int s = 0; s < 4; s++) a2[s] = g_A2[c * DS + sg * 4 + s];
    const float dpc = Dp[c];

    const size_t base = (size_t)b * LL * DI + (size_t)g * CLEN * DI + c;
    const size_t zoff = (size_t)b * LL * (2 * DI) + (size_t)g * CLEN * (2 * DI) + DI + c;

    const size_t idx = ((size_t)b * DI + c) * GCH + g;
    const float* hi = g_hin + idx * DS + sg * 4;
    float h0 = hi[0], h1 = hi[1], h2 = hi[2], h3 = hi[3];

    float px[8], pd[8];
#pragma unroll
    for (int u = 0; u < 8; u++) {
        const size_t o = base + (size_t)u * DI;
        px[u] = __half2float(g_xacth[o]);
        pd[u] = g_dt[o];
    }

    for (int t0 = 0; t0 < CLEN; t0 += 8) {
        float cx[8], cd[8];
#pragma unroll
        for (int u = 0; u < 8; u++) { cx[u] = px[u]; cd[u] = pd[u]; }
        if (t0 + 8 < CLEN) {
#pragma unroll
            for (int u = 0; u < 8; u++) {
                const size_t o = base + (size_t)(t0 + 8 + u) * DI;
                px[u] = __half2float(g_xacth[o]);
                pd[u] = g_dt[o];
            }
        }
#pragma unroll
        for (int u = 0; u < 8; u++) {
            const float xv  = cx[u];
            const float dv  = cd[u];
            const float dtx = dv * xv;
            h0 = ex2f(dv * a2[0]) * h0 + dtx;
            h1 = ex2f(dv * a2[1]) * h1 + dtx;
            h2 = ex2f(dv * a2[2]) * h2 + dtx;
            h3 = ex2f(dv * a2[3]) * h3 + dtx;
            float sum = (h0 + h1) + (h2 + h3);
            sum += __shfl_xor_sync(0xffffffffu, sum, 1);
            sum += __shfl_xor_sync(0xffffffffu, sum, 2);
            if (sg == 0) {
                const float zs = g_xz[zoff + (size_t)(t0 + u) * (2 * DI)];
                const float v  = (sum + dpc * xv) * zs;
                g_ygh[base + (size_t)(t0 + u) * DI] = __float2half_rn(v);
            }
        }
    }
}

// ---------------- launch -------------------------------------------------------
extern "C" void kernel_launch(void* const* d_in, const int* in_sizes, int n_in,
                              void* d_out, int out_size)
{
    (void)in_sizes; (void)n_in; (void)out_size;
    const float* x     = (const float*)d_in[0];
    const float* W_in  = (const float*)d_in[1];
    const float* cw    = (const float*)d_in[2];
    const float* cb    = (const float*)d_in[3];
    const float* A_log = (const float*)d_in[4];
    const float* Dp    = (const float*)d_in[5];
    const float* W_dt  = (const float*)d_in[6];
    const float* b_dt  = (const float*)d_in[7];
    const float* W_out = (const float*)d_in[8];
    float* out = (float*)d_out;

    float *xz, *dt;
    __half *xh, *winh, *wdth, *wouth, *xacth, *ygh;
    cudaGetSymbolAddress((void**)&xz,    g_xz);
    cudaGetSymbolAddress((void**)&dt,    g_dt);
    cudaGetSymbolAddress((void**)&xh,    g_xh);
    cudaGetSymbolAddress((void**)&winh,  g_Winh);
    cudaGetSymbolAddress((void**)&wdth,  g_Wdth);
    cudaGetSymbolAddress((void**)&wouth, g_Wouth);
    cudaGetSymbolAddress((void**)&xacth, g_xacth);
    cudaGetSymbolAddress((void**)&ygh,   g_ygh);

    cudaFuncSetAttribute(mma_gemm<2 * DI, DM, 1>,
                         cudaFuncAttributeMaxDynamicSharedMemorySize, GEMM_SMEM);
    cudaFuncSetAttribute(mma_gemm<DI, DI, 2>,
                         cudaFuncAttributeMaxDynamicSharedMemorySize, GEMM_SMEM);
    cudaFuncSetAttribute(mma_gemm<DM, DI, 0>,
                         cudaFuncAttributeMaxDynamicSharedMemorySize, GEMM_SMEM);

    // launches #1..#3 (profiler captures the 4th launch -> gemm1)
    prep_A2_kernel<<<(DI * DS + 255) / 256, 256>>>(A_log);
    cvt_kernel<<<(MM * DM / 4 + 255) / 256, 256>>>(x,    xh,   MM * DM / 4);
    cvt_kernel<<<(2 * DI * DM / 4 + 255) / 256, 256>>>(W_in, winh, 2 * DI * DM / 4);

    // #4: GEMM1: xz = x @ W_in^T  (silu fused on z half)   <-- profiled
    mma_gemm<2 * DI, DM, 1><<<dim3((2 * DI) / 128, MM / 128), 512, GEMM_SMEM>>>(
        xh, winh, xz, nullptr);

    cvt_kernel<<<(DI * DI / 4 + 255) / 256, 256>>>(W_dt, wdth, DI * DI / 4);
    conv_silu_kernel<<<(MM * DI + 255) / 256, 256>>>(cw, cb);

    // GEMM2: dt = softplus(x_act @ W_dt^T + b_dt)
    mma_gemm<DI, DI, 2><<<dim3(DI / 128, MM / 128), 512, GEMM_SMEM>>>(
        xacth, wdth, dt, b_dt);

    cvt_kernel<<<(DM * DI / 4 + 255) / 256, 256>>>(W_out, wouth, DM * DI / 4);

    // chunked scan
    scanA_kernel<<<BB * (DI / 32) * GCH, 128>>>();
    scanB_kernel<<<(BB * DI * 4 + 255) / 256, 256>>>();
    scanC_kernel<<<BB * (DI / 32) * GCH, 128>>>(Dp);

    // GEMM3: out = yg @ W_out^T
    mma_gemm<DM, DI, 0><<<dim3(DM / 128, MM / 128), 512, GEMM_SMEM>>>(
        ygh, wouth, out, nullptr);
}